// round 15
// baseline (speedup 1.0000x reference)
#include <cuda_runtime.h>
#include <math.h>

// ---------------------------------------------------------------------------
// MetaQDA via conditioned Woodbury / matrix-determinant-lemma restructuring.
//   S_c = L L^T + V_c^T V_c,   V_c = [x_i - xbar (32 rows); sqrt(kappa*N/kN)(xbar - m)]
//   S^{-1} = L^{-T}(I - T^T M^{-1} T)L^{-1},  T = V L^{-T} (33 x D),  M = I + T T^T (SPD)
//   logdet S = 2 sum log|L_ii| + logdet M
// This round: Cholesky factor R = Lc^{-1} of M folded INTO T before the U GEMM
// (v^T M^{-1} v = ||R v||^2), so finalize does 33 FMA instead of a 33x33
// quadratic form; U K-split reduce folded into finalize; inv_diag64 reverted
// to the non-spilling serial-chain version.
// ---------------------------------------------------------------------------

#define Dd   1024
#define Cc   32
#define SHOTSn 32
#define NSUP 1024
#define Qq   1024
#define KW   34     // rows of T-hat per class: 32 centered + scaled-diff + mu(aux)
#define KV   33     // rows entering the Woodbury capacitance M
#define NU   (Cc * KW)   // 1088
#define NUQ  (NU + Qq)   // 2112
#define DSPL 8           // dual K-split chunks (kchunk = 128)
#define USPL 4           // U K-split chunks

// ------------------------- scratch (device globals) -------------------------
__device__ float g_L[Dd * Dd];
__device__ float g_Linv[Dd * Dd];
__device__ float g_Tmp[512 * 512];
__device__ float g_W[NU * Dd];
__device__ float g_TG[NUQ * Dd];        // T (first NU rows) then G (Qq rows)
__device__ float g_Part[DSPL * NUQ * Dd];  // K-split partial buffer
__device__ float g_TtT[Cc * KW * KW];
__device__ float g_R[Cc * KV * KV];     // R = Lc^{-1} per class (fp32)
__device__ float g_b[Cc * KW];          // b' = R b per class
__device__ float g_mu[Cc * Dd];
__device__ float g_xbar[Cc * Dd];
__device__ float g_Gn2[Qq];
__device__ float g_qn2[Qq];
__device__ float g_mun2[Cc];
__device__ float g_qm[Qq * Cc];
__device__ int   g_sample_of[Cc * SHOTSn];

struct Cls {
    float Nj, kN, common_, scale;
    float bias, coefD, inv_common, invscale_half, hh;
};
__device__ Cls   g_cls[Cc];
__device__ float g_kappa_;
__device__ float g_sumlogL;

// ------------------------------ f32x2 helpers --------------------------------
__device__ __forceinline__ unsigned long long ffma2(unsigned long long a,
                                                    unsigned long long b,
                                                    unsigned long long c) {
    unsigned long long d;
    asm("fma.rn.f32x2 %0, %1, %2, %3;" : "=l"(d) : "l"(a), "l"(b), "l"(c));
    return d;
}
__device__ __forceinline__ unsigned long long pack2(float lo, float hi) {
    unsigned long long r;
    asm("mov.b64 %0, {%1, %2};" : "=l"(r) : "f"(lo), "f"(hi));
    return r;
}

// ------------------------------- setup --------------------------------------
__global__ void setup_kernel(const int* __restrict__ labels,
                             const float* __restrict__ kappa_p,
                             const float* __restrict__ nu_p,
                             const float* __restrict__ triu_diag) {
    __shared__ int   hist[32][33];   // [warp][class]
    __shared__ float red[32];
    int t = threadIdx.x;  // 1024 threads
    int w = t >> 5, lane = t & 31;
    hist[w][lane] = 0;
    g_sample_of[t] = 0;
    __syncthreads();

    int l = labels[t];
    unsigned mask = __match_any_sync(0xffffffffu, l);
    int intra = __popc(mask & ((1u << lane) - 1u));
    int leader = __ffs(mask) - 1;
    if (lane == leader && l >= 0 && l < Cc) hist[w][l] = __popc(mask);
    __syncthreads();
    if (l >= 0 && l < Cc) {
        int cnt = intra;
        for (int w2 = 0; w2 < w; w2++) cnt += hist[w2][l];
        if (cnt < SHOTSn) g_sample_of[l * SHOTSn + cnt] = t;
    }

    float v = logf(fabsf(triu_diag[t]));
    for (int o = 16; o > 0; o >>= 1) v += __shfl_down_sync(0xffffffffu, v, o);
    if (lane == 0) red[w] = v;
    __syncthreads();
    if (t < 32) {
        float s = red[t];
        for (int o = 16; o > 0; o >>= 1) s += __shfl_down_sync(0xffffffffu, s, o);
        if (t == 0) g_sumlogL = s;
    }

    if (t < Cc) {
        int nj = 0;
        for (int w2 = 0; w2 < 32; w2++) nj += hist[w2][t];
        float kappa_ = fabsf(*kappa_p) + 1e-6f;
        float nu_    = fmaxf(*nu_p, (float)(Dd - 1) + 1e-6f);
        float Njf = (float)nj;
        float kN = kappa_ + Njf;
        float common_ = nu_ + Njf + 1.0f - (float)Dd;
        float scale = (kN + 1.0f) / (common_ * kN);
        Cls c;
        c.Nj = Njf; c.kN = kN; c.common_ = common_; c.scale = scale;
        c.bias = 0.f;
        c.coefD = 0.5f * (common_ + (float)Dd);
        c.inv_common = 1.0f / common_;
        c.invscale_half = 0.5f / scale;
        c.hh = 0.f;
        g_cls[t] = c;
        if (t == 0) g_kappa_ = kappa_;
    }
}

// --------------------------- build L (and zero Linv) -------------------------
__global__ void build_L_kernel(const float* __restrict__ tdiag,
                               const float* __restrict__ tlower) {
    int idx = blockIdx.x * blockDim.x + threadIdx.x;
    if (idx >= Dd * Dd) return;
    int i = idx / Dd, j = idx % Dd;
    float v = (i == j) ? fabsf(tdiag[i]) : (i > j ? tlower[idx] : 0.0f);
    g_L[idx] = v;
    g_Linv[idx] = 0.0f;
}

// --------- invert 64x64 lower-triangular diagonal blocks (registers) ---------
// R12 version: plain serial chain (96 regs, no spill).
__global__ void inv_diag64_kernel() {
    __shared__ float Ls[64][65];
    __shared__ float rd[64];
    int b = blockIdx.x, t = threadIdx.x;  // 64 threads
    int off = b * 64;
    for (int i = 0; i < 64; i++) Ls[i][t] = g_L[(long long)(off + i) * Dd + off + t];
    __syncthreads();
    rd[t] = 1.0f / Ls[t][t];
    __syncthreads();
    float x[64];
#pragma unroll
    for (int i = 0; i < 64; i++) {
        float s = (t == i) ? 1.0f : 0.0f;
#pragma unroll
        for (int k = 0; k < i; k++) s -= Ls[i][k] * x[k];
        x[i] = s * rd[i];
    }
#pragma unroll
    for (int i = 0; i < 64; i++)
        g_Linv[(long long)(off + i) * Dd + off + t] = x[i];
}

// -------- fast SGEMM core (128x128x8, 8x8 via f32x2, dbuf, conflict-free) ----
template <bool TRANSB>
__device__ __forceinline__ void sgemm128_core(
    const float* __restrict__ A, int lda,
    const float* __restrict__ B, int ldb,
    float* __restrict__ Cp, int ldc,
    int M, int N, float alpha, int m0, int n0, int kbeg, int kend) {
    __shared__ __align__(16) float Asd[2][8][264];  // [k][2*m] duplicated
    __shared__ __align__(16) float Bs[2][8][132];   // [k][n]
    const int tid = threadIdx.x;              // 256
    const int tx = tid & 15, ty = tid >> 4;
    const int arow = tid >> 1, ak4 = (tid & 1) * 4;   // A (and B if TRANSB) loads
    const int bk = tid >> 5, bn4 = (tid & 31) * 4;    // B loads if !TRANSB

    unsigned long long acc2[8][4] = {};  // 8 m-rows x 4 packed n-pairs

    if (kend > kbeg) {
        const int t0 = kbeg >> 3, t1 = kend >> 3;
        float4 ar, br;
        const float4 fz = make_float4(0.f, 0.f, 0.f, 0.f);

        ar = (m0 + arow < M) ? *(const float4*)(A + (long long)(m0 + arow) * lda + kbeg + ak4) : fz;
        if (TRANSB) {
            br = (n0 + arow < N) ? *(const float4*)(B + (long long)(n0 + arow) * ldb + kbeg + ak4) : fz;
        } else {
            if (n0 + bn4 + 3 < N) {
                br = *(const float4*)(B + (long long)(kbeg + bk) * ldb + n0 + bn4);
            } else {
                const float* Bp = B + (long long)(kbeg + bk) * ldb;
                br.x = (n0 + bn4 + 0 < N) ? Bp[n0 + bn4 + 0] : 0.f;
                br.y = (n0 + bn4 + 1 < N) ? Bp[n0 + bn4 + 1] : 0.f;
                br.z = (n0 + bn4 + 2 < N) ? Bp[n0 + bn4 + 2] : 0.f;
                br.w = (n0 + bn4 + 3 < N) ? Bp[n0 + bn4 + 3] : 0.f;
            }
        }
        *(float2*)&Asd[0][ak4 + 0][2 * arow] = make_float2(ar.x, ar.x);
        *(float2*)&Asd[0][ak4 + 1][2 * arow] = make_float2(ar.y, ar.y);
        *(float2*)&Asd[0][ak4 + 2][2 * arow] = make_float2(ar.z, ar.z);
        *(float2*)&Asd[0][ak4 + 3][2 * arow] = make_float2(ar.w, ar.w);
        if (TRANSB) {
            Bs[0][ak4 + 0][arow] = br.x; Bs[0][ak4 + 1][arow] = br.y;
            Bs[0][ak4 + 2][arow] = br.z; Bs[0][ak4 + 3][arow] = br.w;
        } else {
            *(float4*)&Bs[0][bk][bn4] = br;
        }
        __syncthreads();

        for (int t = t0; t < t1; t++) {
            const int buf = (t - t0) & 1;
            const int kn = (t + 1) << 3;
            if (t + 1 < t1) {
                ar = (m0 + arow < M) ? *(const float4*)(A + (long long)(m0 + arow) * lda + kn + ak4) : fz;
                if (TRANSB) {
                    br = (n0 + arow < N) ? *(const float4*)(B + (long long)(n0 + arow) * ldb + kn + ak4) : fz;
                } else {
                    if (n0 + bn4 + 3 < N) {
                        br = *(const float4*)(B + (long long)(kn + bk) * ldb + n0 + bn4);
                    } else {
                        const float* Bp = B + (long long)(kn + bk) * ldb;
                        br.x = (n0 + bn4 + 0 < N) ? Bp[n0 + bn4 + 0] : 0.f;
                        br.y = (n0 + bn4 + 1 < N) ? Bp[n0 + bn4 + 1] : 0.f;
                        br.z = (n0 + bn4 + 2 < N) ? Bp[n0 + bn4 + 2] : 0.f;
                        br.w = (n0 + bn4 + 3 < N) ? Bp[n0 + bn4 + 3] : 0.f;
                    }
                }
            }
#pragma unroll
            for (int k = 0; k < 8; k++) {
                unsigned long long a2[8], b2[4];
#pragma unroll
                for (int i = 0; i < 8; i++)
                    a2[i] = *(const unsigned long long*)&Asd[buf][k][(ty * 8 + i) * 2];
                float4 bf0 = *(const float4*)&Bs[buf][k][tx * 8];
                float4 bf1 = *(const float4*)&Bs[buf][k][tx * 8 + 4];
                b2[0] = pack2(bf0.x, bf0.y);
                b2[1] = pack2(bf0.z, bf0.w);
                b2[2] = pack2(bf1.x, bf1.y);
                b2[3] = pack2(bf1.z, bf1.w);
#pragma unroll
                for (int i = 0; i < 8; i++)
#pragma unroll
                    for (int j = 0; j < 4; j++) acc2[i][j] = ffma2(a2[i], b2[j], acc2[i][j]);
            }
            if (t + 1 < t1) {
                const int b2i = (t + 1 - t0) & 1;
                *(float2*)&Asd[b2i][ak4 + 0][2 * arow] = make_float2(ar.x, ar.x);
                *(float2*)&Asd[b2i][ak4 + 1][2 * arow] = make_float2(ar.y, ar.y);
                *(float2*)&Asd[b2i][ak4 + 2][2 * arow] = make_float2(ar.z, ar.z);
                *(float2*)&Asd[b2i][ak4 + 3][2 * arow] = make_float2(ar.w, ar.w);
                if (TRANSB) {
                    Bs[b2i][ak4 + 0][arow] = br.x; Bs[b2i][ak4 + 1][arow] = br.y;
                    Bs[b2i][ak4 + 2][arow] = br.z; Bs[b2i][ak4 + 3][arow] = br.w;
                } else {
                    *(float4*)&Bs[b2i][bk][bn4] = br;
                }
            }
            __syncthreads();
        }
    }

#pragma unroll
    for (int i = 0; i < 8; i++) {
        int m = m0 + ty * 8 + i;
        if (m >= M) continue;
        float* Cr = Cp + (long long)m * ldc;
#pragma unroll
        for (int j = 0; j < 4; j++) {
            int n = n0 + tx * 8 + 2 * j;
            float lo = __uint_as_float((unsigned int)acc2[i][j]);
            float hi = __uint_as_float((unsigned int)(acc2[i][j] >> 32));
            if (n < N)     Cr[n]     = alpha * lo;
            if (n + 1 < N) Cr[n + 1] = alpha * hi;
        }
    }
}

// -------------------- K-split wrapper: writes partial chunks -----------------
template <bool TRANSB>
__global__ __launch_bounds__(256)
void sgemm128_split_kernel(const float* __restrict__ A, long long sA, int lda,
                           const float* __restrict__ B, long long sB, int ldb,
                           float* __restrict__ part,
                           int M, int N, int K, int nsplit, int kchunk,
                           int kbmode, int kemode) {
    int pair = blockIdx.z / nsplit;
    int chunk = blockIdx.z % nsplit;
    int m0 = blockIdx.y * 128, n0 = blockIdx.x * 128;
    int kb = chunk * kchunk;
    int ke = min(kb + kchunk, K);
    if (kbmode == 1) kb = max(kb, n0);
    if (kemode == 1) ke = min(ke, m0 + 128);
    float* Cp = part + (long long)blockIdx.z * M * N;
    sgemm128_core<TRANSB>(A + pair * sA, lda, B + pair * sB, ldb,
                          Cp, N, M, N, 1.0f, m0, n0, kb, ke);
}

// -------------------- direct (no-split) wrapper ------------------------------
template <bool TRANSB>
__global__ __launch_bounds__(256)
void sgemm128_direct_kernel(const float* __restrict__ A, long long sA, int lda,
                            const float* __restrict__ B, long long sB, int ldb,
                            float* __restrict__ Cp, long long sC, int ldc,
                            int M, int N, int K, float alpha, int kbmode, int kemode) {
    int m0 = blockIdx.y * 128, n0 = blockIdx.x * 128;
    int kb = (kbmode == 1) ? n0 : 0;
    int ke = (kemode == 1) ? min(K, m0 + 128) : K;
    sgemm128_core<TRANSB>(A + blockIdx.z * sA, lda, B + blockIdx.z * sB, ldb,
                          Cp + blockIdx.z * sC, ldc, M, N, alpha, m0, n0, kb, ke);
}

// Fused T|G (stacked) = [W; query] @ Linv^T, uniform K=128 chunks with
// triangle-aware validity.
__global__ __launch_bounds__(256)
void sgemm128_dual_split_kernel(const float* __restrict__ A1, int nby1,
                                const float* __restrict__ A2,
                                const float* __restrict__ B,
                                float* __restrict__ part) {
    int chunk = blockIdx.z;
    int n0 = blockIdx.x * 128;
    int kb = chunk * 128;
    if (kb > n0) return;                 // chunk past the triangle: no work
    int ke = kb + 128;
    const float* A;
    int M, m0, rowoff;
    if ((int)blockIdx.y < nby1) {
        A = A1; M = NU; m0 = blockIdx.y * 128; rowoff = 0;
    } else {
        A = A2; M = Qq; m0 = (blockIdx.y - nby1) * 128; rowoff = NU;
    }
    float* Cp = part + (long long)chunk * NUQ * Dd + (long long)rowoff * Dd;
    sgemm128_core<true>(A, Dd, B, Dd, Cp, Dd, M, Dd, 1.0f, m0, n0, kb, ke);
}

// ---- triangle-aware reduce for dual: column j sums chunks 0..j only --------
__global__ void reduce_tri_kernel(const float* __restrict__ part, float* __restrict__ out) {
    long long idx = (long long)blockIdx.x * blockDim.x + threadIdx.x;
    long long total = (long long)NUQ * Dd;
    if (idx >= total) return;
    int nn = (int)(idx % Dd);
    int cnt = (nn >> 7) + 1;            // column block j = nn/128 -> j+1 chunks
    const float* p = part + idx;
    float s = 0.f;
    for (int c = 0; c < cnt; c++) s += p[(long long)c * NUQ * Dd];
    out[idx] = s;
}

// -------------------- reduce partial chunks into output ----------------------
__global__ void reduce_kernel(const float* __restrict__ part, float* __restrict__ out,
                              int nsplit, int M, int N, int ldc, long long sOut,
                              float alpha, int pairs) {
    long long idx = (long long)blockIdx.x * blockDim.x + threadIdx.x;
    long long total = (long long)pairs * M * N;
    if (idx >= total) return;
    int pair = (int)(idx / ((long long)M * N));
    long long rem = idx - (long long)pair * M * N;
    int mm = (int)(rem / N);
    int nn = (int)(rem - (long long)mm * N);
    const float* p = part + (long long)pair * nsplit * M * N + rem;
    float s = 0.f;
    for (int c = 0; c < nsplit; c++) s += p[(long long)c * M * N];
    out[pair * sOut + (long long)mm * ldc + nn] = alpha * s;
}

// ----------------- fused per-class means + W build ---------------------------
__global__ void build_WM_kernel(const float* __restrict__ support,
                                const float* __restrict__ m) {
    int idx = blockIdx.x * blockDim.x + threadIdx.x;  // over C * D
    if (idx >= Cc * Dd) return;
    int c = idx / Dd, d = idx % Dd;
    const int* so = g_sample_of + c * SHOTSn;
    float mv = m[d];
    float s = 0.f;
#pragma unroll 4
    for (int j = 0; j < SHOTSn; j++)
        s += support[(long long)so[j] * Dd + d];
    Cls cl = g_cls[c];
    float xbar = s / cl.Nj;
    float mu = (g_kappa_ * mv + s) / cl.kN;
    g_xbar[idx] = xbar;
    g_mu[idx] = mu;
    float* Wc = g_W + (long long)(c * KW) * Dd + d;
#pragma unroll 4
    for (int k = 0; k < SHOTSn; k++)
        Wc[(long long)k * Dd] = support[(long long)so[k] * Dd + d] - xbar;
    float c2 = sqrtf(g_kappa_ * cl.Nj / cl.kN);
    Wc[(long long)SHOTSn * Dd] = c2 * (xbar - mv);
    Wc[(long long)(SHOTSn + 1) * Dd] = mu;
}

// ---------------- all row norms in one launch (G, query, mu) -----------------
__global__ void rownorm_all_kernel(const float* __restrict__ G,
                                   const float* __restrict__ query) {
    int r = blockIdx.x, t = threadIdx.x;  // 256 threads
    const float* row;
    float* dst;
    if (r < Qq)            { row = G + (long long)r * Dd;            dst = g_Gn2 + r; }
    else if (r < 2 * Qq)   { row = query + (long long)(r - Qq) * Dd; dst = g_qn2 + (r - Qq); }
    else                   { row = g_mu + (long long)(r - 2 * Qq) * Dd; dst = g_mun2 + (r - 2 * Qq); }
    float s = 0.f;
    for (int j = t; j < Dd; j += blockDim.x) { float v = row[j]; s += v * v; }
    __shared__ float red[8];
    for (int o = 16; o > 0; o >>= 1) s += __shfl_down_sync(0xffffffffu, s, o);
    if ((t & 31) == 0) red[t >> 5] = s;
    __syncthreads();
    if (t < 32) {
        float v = (t < 8) ? red[t] : 0.f;
        for (int o = 4; o > 0; o >>= 1) v += __shfl_down_sync(0xffffffffu, v, o);
        if (t == 0) *dst = v;
    }
}

// ---------------- K-split Gram: TtT partials per (class, chunk) --------------
__global__ void gram_split_kernel(const float* __restrict__ T,
                                  float* __restrict__ part,
                                  int nsplit, int kchunk) {
    __shared__ __align__(16) float Ts[KW][256 + 4];
    int c = blockIdx.x / nsplit;
    int chunk = blockIdx.x % nsplit;
    int tid = threadIdx.x;  // 256
    const float* Tc = T + (long long)(c * KW) * Dd + chunk * kchunk;
    for (int i = tid; i < KW * (kchunk / 4); i += blockDim.x) {
        int row = i / (kchunk / 4), k4 = (i % (kchunk / 4)) * 4;
        *(float4*)&Ts[row][k4] = *(const float4*)(Tc + (long long)row * Dd + k4);
    }
    __syncthreads();
    float* outp = part + (long long)blockIdx.x * KW * KW;
    for (int e = tid; e < KW * KW; e += blockDim.x) {
        int i = e / KW, j = e % KW;
        float s = 0.f;
        for (int k = 0; k < kchunk; k += 4) {
            float4 a = *(const float4*)&Ts[i][k];
            float4 b = *(const float4*)&Ts[j][k];
            s += a.x * b.x + a.y * b.y + a.z * b.z + a.w * b.w;
        }
        outp[e] = s;
    }
}

// ------------------------- skinny qm = query @ mu^T --------------------------
__global__ void qm_kernel(const float* __restrict__ query) {
    __shared__ __align__(16) float mus[32][68];
    int tid = threadIdx.x;  // 256
    int c = tid & 31, qi = tid >> 5;  // 8 q per block
    int q = blockIdx.x * 8 + qi;
    float acc = 0.f;
    for (int k0 = 0; k0 < Dd; k0 += 64) {
        for (int i = tid; i < 32 * 16; i += 256) {
            int row = i / 16, k4 = (i % 16) * 4;
            *(float4*)&mus[row][k4] = *(const float4*)(g_mu + (long long)row * Dd + k0 + k4);
        }
        __syncthreads();
        const float* qr = query + (long long)q * Dd + k0;
#pragma unroll
        for (int k = 0; k < 64; k += 4) {
            float4 qv = *(const float4*)(qr + k);     // broadcast across warp
            float4 mv = *(const float4*)&mus[c][k];
            acc += qv.x * mv.x + qv.y * mv.y + qv.z * mv.z + qv.w * mv.w;
        }
        __syncthreads();
    }
    g_qm[(long long)q * Cc + c] = acc;
}

// ---- per-class fp64 Cholesky of M = I + T T^T, R = Lc^{-1}, b' = R b --------
// M is SPD with lambda_min = 1 (no pivoting needed, all pivots >= 1).
__global__ void small_chol_kernel() {
    int c = blockIdx.x, t = threadIdx.x;  // 64 threads
    __shared__ double Ms[KV][KV + 1];     // becomes Lc (lower, diag = d)
    __shared__ double Ri[KV][KV + 1];     // Lc^{-1}
    __shared__ double bb[KV];
    __shared__ double s_logdet;
    const float* TtT = g_TtT + c * KW * KW;
    for (int i = t; i < KV * KV; i += blockDim.x) {
        int r = i / KV, cc = i % KV;
        Ms[r][cc] = (double)TtT[r * KW + cc] + (r == cc ? 1.0 : 0.0);
    }
    if (t < KV) bb[t] = (double)TtT[t * KW + (KW - 1)];  // b_i = t_i . t_mu
    if (t == 0) s_logdet = 0.0;
    __syncthreads();
    // right-looking Cholesky
    for (int k = 0; k < KV; k++) {
        if (t == 0) {
            double d = sqrt(Ms[k][k]);
            Ms[k][k] = d;
            s_logdet += 2.0 * log(d);
        }
        __syncthreads();
        double dinv = 1.0 / Ms[k][k];
        for (int i = k + 1 + t; i < KV; i += blockDim.x) Ms[i][k] *= dinv;
        __syncthreads();
        for (int e = t; e < KV * KV; e += blockDim.x) {
            int i = e / KV, j = e % KV;
            if (j > k && j <= i) Ms[i][j] -= Ms[i][k] * Ms[j][k];
        }
        __syncthreads();
    }
    // invert Lc: column t by forward substitution (thread-owned column)
    if (t < KV) {
        for (int i = 0; i < KV; i++) {
            double s = (i == t) ? 1.0 : 0.0;
            for (int k2 = t; k2 < i; k2++) s -= Ms[i][k2] * Ri[k2][t];
            Ri[i][t] = (i >= t) ? s / Ms[i][i] : 0.0;
        }
    }
    __syncthreads();
    // b' = Ri @ b
    if (t < KV) {
        double s = 0.0;
        for (int k2 = 0; k2 <= t; k2++) s += Ri[t][k2] * bb[k2];
        g_b[c * KW + t] = (float)s;
    }
    for (int i = t; i < KV * KV; i += blockDim.x)
        g_R[c * KV * KV + i] = (float)Ri[i / KV][i % KV];
    if (t == 0) {
        Cls cl = g_cls[c];
        double logdetS = 2.0 * (double)g_sumlogL + s_logdet;
        double logdet_sigma = (double)Dd * log((double)cl.scale) + logdetS;
        double common_ = (double)cl.common_;
        double bias = lgamma(0.5 * (common_ + (double)Dd)) - lgamma(0.5 * common_)
                    - 0.5 * (double)Dd * log(common_) - 0.5 * logdet_sigma;
        g_cls[c].bias = (float)bias;
        g_cls[c].hh = TtT[(KW - 1) * KW + (KW - 1)];  // ||t_mu||^2
    }
}

// ---- transform T rows 0..32 in place: T' = R @ T (row 33 = t_mu untouched) --
__global__ void transformT_kernel() {
    __shared__ __align__(16) float Ts[KV][132];
    __shared__ float Rs[KV][KV + 3];
    int c = blockIdx.y;
    int d0 = blockIdx.x * 128;
    int tid = threadIdx.x;  // 256
    float* Tc = g_TG + (long long)(c * KW) * Dd + d0;
    for (int i = tid; i < KV * 32; i += 256) {
        int r = i / 32, k4 = (i % 32) * 4;
        *(float4*)&Ts[r][k4] = *(const float4*)(Tc + (long long)r * Dd + k4);
    }
    for (int i = tid; i < KV * KV; i += 256) Rs[i / KV][i % KV] = g_R[c * KV * KV + i];
    __syncthreads();
    int col = tid & 127;
    int r0 = (tid < 128) ? 0 : 17;
    int r1 = (tid < 128) ? 17 : KV;
    float o[17];
    for (int i = r0; i < r1; i++) {
        float s = 0.f;
        for (int k = 0; k <= i; k++) s += Rs[i][k] * Ts[k][col];
        o[i - r0] = s;
    }
    // writes go to global; reads were from smem copy -> no sync needed
    for (int i = r0; i < r1; i++) Tc[(long long)i * Dd + col] = o[i - r0];
}

// --------------------------------- finalize ----------------------------------
// Reads the U K-split partials directly (sum of USPL chunks), then
// dist term = Gn2 - 2*u33 + hh - ||u' - b'||^2.
__global__ void finalize_kernel(const float* __restrict__ part, float* __restrict__ out) {
    int c = blockIdx.y;
    int q = blockIdx.x * blockDim.x + threadIdx.x;
    __shared__ float bs[KV];
    __shared__ Cls cl;
    if (threadIdx.x < KV) bs[threadIdx.x] = g_b[c * KW + threadIdx.x];
    if (threadIdx.x == 0) cl = g_cls[c];
    __syncthreads();
    if (q >= Qq) return;
    const float* U0 = part + (long long)q * NU + c * KW;
    const long long cs = (long long)Qq * NU;
    float s = 0.f, u33;
#pragma unroll
    for (int i = 0; i < KW; i++) {
        float u = U0[i] + U0[cs + i] + U0[2 * cs + i] + U0[3 * cs + i];
        if (i < KV) {
            float v = u - bs[i];
            s += v * v;
        } else {
            u33 = u;
        }
    }
    float distA = g_Gn2[q] - 2.0f * u33 + cl.hh - s;
    float dist  = cl.invscale_half * distA
                + 0.5f * (g_qn2[q] - 2.0f * g_qm[q * Cc + c] + g_mun2[c]);
    out[(long long)q * Cc + c] = cl.bias - cl.coefD * log1pf(dist * cl.inv_common);
}

// ------------------------------ host launchers -------------------------------
static void sgemm_big_split(const float* A, long long sA, int lda,
                            const float* B, long long sB, int ldb,
                            float* part, float* out, long long sOut, int ldc,
                            int M, int N, int K, float alpha, bool transB, int pairs,
                            int nsplit, int kchunk, int kbmode, int kemode) {
    dim3 grid((N + 127) / 128, (M + 127) / 128, pairs * nsplit);
    if (transB)
        sgemm128_split_kernel<true><<<grid, 256>>>(A, sA, lda, B, sB, ldb, part,
                                                   M, N, K, nsplit, kchunk, kbmode, kemode);
    else
        sgemm128_split_kernel<false><<<grid, 256>>>(A, sA, lda, B, sB, ldb, part,
                                                    M, N, K, nsplit, kchunk, kbmode, kemode);
    long long total = (long long)pairs * M * N;
    reduce_kernel<<<(unsigned)((total + 255) / 256), 256>>>(part, out, nsplit, M, N, ldc,
                                                            sOut, alpha, pairs);
}

static void sgemm_big_direct(const float* A, long long sA, int lda,
                             const float* B, long long sB, int ldb,
                             float* Cmat, long long sC, int ldc,
                             int M, int N, int K, float alpha, bool transB, int pairs,
                             int kbmode, int kemode) {
    dim3 grid((N + 127) / 128, (M + 127) / 128, pairs);
    if (transB)
        sgemm128_direct_kernel<true><<<grid, 256>>>(A, sA, lda, B, sB, ldb, Cmat, sC, ldc,
                                                    M, N, K, alpha, kbmode, kemode);
    else
        sgemm128_direct_kernel<false><<<grid, 256>>>(A, sA, lda, B, sB, ldb, Cmat, sC, ldc,
                                                     M, N, K, alpha, kbmode, kemode);
}

extern "C" void kernel_launch(void* const* d_in, const int* in_sizes, int n_in,
                              void* d_out, int out_size) {
    const float* support = (const float*)d_in[0];
    const float* query   = (const float*)d_in[1];
    const int*   labels  = (const int*)d_in[2];
    const float* m       = (const float*)d_in[3];
    const float* kappa   = (const float*)d_in[4];
    const float* nu      = (const float*)d_in[5];
    const float* tdiag   = (const float*)d_in[6];
    const float* tlower  = (const float*)d_in[7];
    float* out = (float*)d_out;

    float *pL, *pLinv, *pTmp, *pW, *pTG, *pPart, *pTtT;
    cudaGetSymbolAddress((void**)&pL, g_L);
    cudaGetSymbolAddress((void**)&pLinv, g_Linv);
    cudaGetSymbolAddress((void**)&pTmp, g_Tmp);
    cudaGetSymbolAddress((void**)&pW, g_W);
    cudaGetSymbolAddress((void**)&pTG, g_TG);
    cudaGetSymbolAddress((void**)&pPart, g_Part);
    cudaGetSymbolAddress((void**)&pTtT, g_TtT);
    float* pT = pTG;                        // T: rows 0..NU-1
    float* pG = pTG + (long long)NU * Dd;   // G: rows NU..NU+Qq-1

    // 1) scalars, per-class params, parallel-rank sample gather, sum log|diag L|
    setup_kernel<<<1, NSUP>>>(labels, kappa, nu, tdiag);

    // 2) fused per-class xbar/mu + W = [X_c - xbar | sqrt(.)*(xbar-m) | mu_c]
    build_WM_kernel<<<(Cc * Dd + 255) / 256, 256>>>(support, m);

    // 3) L and L^{-1} (recursive-doubling blocked triangular inverse, 64-base)
    build_L_kernel<<<(Dd * Dd + 255) / 256, 256>>>(tdiag, tlower);
    inv_diag64_kernel<<<16, 64>>>();
    // s = 64 level: 8 pairs, direct
    {
        int s = 64, pairs = 8;
        long long stride = 2LL * s * (Dd + 1);
        sgemm_big_direct(pL + (long long)s * Dd, stride, Dd,
                         pLinv, stride, Dd,
                         pTmp, (long long)s * s, s,
                         s, s, s, 1.0f, false, pairs, 0, 0);
        sgemm_big_direct(pLinv + (long long)s * Dd + s, stride, Dd,
                         pTmp, (long long)s * s, s,
                         pLinv + (long long)s * Dd, stride, Dd,
                         s, s, s, -1.0f, false, pairs, 0, 0);
    }
    // s = 128 level: direct (4 pairs)
    {
        int s = 128, pairs = 4;
        long long stride = 2LL * s * (Dd + 1);
        sgemm_big_direct(pL + (long long)s * Dd, stride, Dd,
                         pLinv, stride, Dd,
                         pTmp, (long long)s * s, s,
                         s, s, s, 1.0f, false, pairs, 1, 0);
        sgemm_big_direct(pLinv + (long long)s * Dd + s, stride, Dd,
                         pTmp, (long long)s * s, s,
                         pLinv + (long long)s * Dd, stride, Dd,
                         s, s, s, -1.0f, false, pairs, 0, 1);
    }
    // s = 256, 512 levels: K-split fast core
    for (int lev = 4; lev <= 5; lev++) {
        int s = 32 << (lev - 1);
        int pairs = 32 >> lev;
        long long stride = 2LL * s * (Dd + 1);
        int nsplit = (s == 256) ? 4 : 8;
        int kchunk = s / nsplit;  // 64
        sgemm_big_split(pL + (long long)s * Dd, stride, Dd,
                        pLinv, stride, Dd,
                        pPart, pTmp, (long long)s * s, s,
                        s, s, s, 1.0f, false, pairs, nsplit, kchunk, 1, 0);
        sgemm_big_split(pLinv + (long long)s * Dd + s, stride, Dd,
                        pTmp, (long long)s * s, s,
                        pPart, pLinv + (long long)s * Dd, stride, Dd,
                        s, s, s, -1.0f, false, pairs, nsplit, kchunk, 0, 1);
    }

    // 4+5) fused: [T; G] = [W; query] @ Linv^T, triangle-aware K=128 chunks
    {
        int nby1 = (NU + 127) / 128;       // 9
        int nby2 = (Qq + 127) / 128;       // 8
        dim3 grid(Dd / 128, nby1 + nby2, DSPL);  // (8, 17, 8)
        sgemm128_dual_split_kernel<<<grid, 256>>>(pW, nby1, query, pLinv, pPart);
        long long total = (long long)NUQ * Dd;
        reduce_tri_kernel<<<(unsigned)((total + 255) / 256), 256>>>(pPart, pTG);
    }

    // 6) all row norms in one launch: ||L^{-1}q||^2, ||q||^2, ||mu||^2
    rownorm_all_kernel<<<2 * Qq + Cc, 256>>>(pG, query);

    // 7) TtT per class (K-split Gram + reduce), then Cholesky/R/b'/bias
    gram_split_kernel<<<Cc * 4, 256>>>(pT, pPart, 4, Dd / 4);
    {
        long long total = (long long)Cc * KW * KW;
        reduce_kernel<<<(unsigned)((total + 255) / 256), 256>>>(pPart, pTtT, 4, KW, KW, KW,
                                                                (long long)KW * KW, 1.0f, Cc);
    }
    small_chol_kernel<<<Cc, 64>>>();

    // 7b) T rows 0..32 <- R @ T (in place; row 33 = t_mu untouched)
    transformT_kernel<<<dim3(Dd / 128, Cc), 256>>>();

    // 8) U' = G @ T'^T  [1024 x 1088], K-split x4, partials consumed by finalize
    {
        dim3 grid((NU + 127) / 128, (Qq + 127) / 128, USPL);
        sgemm128_split_kernel<true><<<grid, 256>>>(pG, 0, Dd, pT, 0, Dd, pPart,
                                                   Qq, NU, Dd, USPL, Dd / USPL, 0, 0);
    }

    // 9) qm = query @ mu^T  [Q x C]  skinny kernel
    qm_kernel<<<Qq / 8, 256>>>(query);

    // 10) finalize: sum U partials, ||u'-b'||^2, bias + log1p
    finalize_kernel<<<dim3((Qq + 127) / 128, Cc), 128>>>(pPart, out);
}